// round 16
// baseline (speedup 1.0000x reference)
#include <cuda_runtime.h>
#include <math.h>

#define NH 8
#define NB 2
#define NSEQ 384
#define NCZ 128
#define NCH 144            // per-head channels: 128 mv + 16 scalar
#define BIGF 100000.0f
#define LNEPS 1e-5f

#define QT 32              // q tile
#define JTT 64             // j tile
#define NJT (NSEQ/JTT)     // 6

// attn smem strides (floats)
#define SQP 36             // sQ [144][36]  (32 cols + pad, float4-aligned)
#define SKP 68             // sK [144][68]  (64 cols + pad, float4-aligned)
#define SVP 148            // sV [64][148]
#define SPP 68             // sP [32][68]
#define ATTN_SMEM_FLOATS (144*SQP + 144*SKP + 64*SVP + 32*SPP)

// bias smem (floats): sZ 128*132 + sA 8*132 + sGB 16 + sM 128 + sR 128 + sMask 128
#define BIAS_PAIRS 128
#define BIAS_SMEM_FLOATS (BIAS_PAIRS*132 + 8*132 + 16 + 128 + 128 + 128)

// Scratch (no cudaMalloc allowed)
__device__ float g_Q[NB*NH*NCH*NSEQ];    // channel-major [b][h][c][n]
__device__ float g_K[NB*NH*NCH*NSEQ];    // channel-major [b][h][c][n]
__device__ float g_V[NB*NH*NSEQ*NCH];    // row-major    [b][h][n][c]
__device__ float g_bias[NB*NH*NSEQ*NSEQ];
__device__ float g_Hb[NB*NSEQ*NH*NCH];

// ---------------- reductions ----------------
__device__ __forceinline__ float warpSum(float v){
#pragma unroll
    for(int o=16;o;o>>=1) v += __shfl_xor_sync(0xffffffffu, v, o);
    return v;
}

template<int NW>
__device__ __forceinline__ float blockSum(float v, float* red){
    int lane = threadIdx.x & 31, w = threadIdx.x >> 5;
    v = warpSum(v);
    if(lane==0) red[w] = v;
    __syncthreads();
    if(threadIdx.x < 32){
        float r = (lane < NW) ? red[lane] : 0.0f;
        r = warpSum(r);
        if(lane==0) red[0] = r;
    }
    __syncthreads();
    float r = red[0];
    __syncthreads();
    return r;
}

__device__ __forceinline__ float grpMax(float v){
#pragma unroll
    for(int o=8;o;o>>=1) v = fmaxf(v, __shfl_xor_sync(0xffffffffu, v, o));
    return v;
}
__device__ __forceinline__ float grpSum(float v){
#pragma unroll
    for(int o=8;o;o>>=1) v += __shfl_xor_sync(0xffffffffu, v, o);
    return v;
}

// ---------------- probes: 2 probes keep the ncu capture slot on bias_kernel ----------------
__global__ void probe_kernel(){}
__global__ void probe_kernel2(){}

// ---------------- Kernel A: pln + QKV projections + rope (unchanged) ----------------
__global__ void qkv_kernel(const float* __restrict__ mv, const float* __restrict__ sca,
                           const float* __restrict__ Wq_mv, const float* __restrict__ Wq_s,
                           const float* __restrict__ Wkv_mv, const float* __restrict__ Wkv_s){
    int bn = blockIdx.x;
    int b = bn / NSEQ, n = bn % NSEQ;
    int t = threadIdx.x;
    __shared__ float mvn[256];
    __shared__ float scn[64];
    __shared__ float qs[128], ks[128], vs[128];
    __shared__ float red[32];
    const float scl = 1.0f/12.0f;  // 1/sqrt(144)

    float x = mv[(size_t)bn*256 + t];
    float s1 = blockSum<8>(x, red);
    float s2 = blockSum<8>(x*x, red);
    float m  = s1 * (1.0f/256.0f);
    float vr = s2 * (1.0f/256.0f) - m*m;
    mvn[t] = (x - m) * rsqrtf(vr + LNEPS);

    float y = (t < 64) ? sca[(size_t)bn*64 + t] : 0.0f;
    float t1 = blockSum<8>(y, red);
    float t2 = blockSum<8>(y*y, red);
    float m2 = t1 * (1.0f/64.0f);
    float v2 = t2 * (1.0f/64.0f) - m2*m2;
    float rs2 = rsqrtf(v2 + LNEPS);
    if(t < 64) scn[t] = (y - m2) * rs2;
    __syncthreads();

    for(int idx = t; idx < 1024; idx += 256){
        int o = idx >> 4, i = idx & 15;
        float a = 0.0f;
#pragma unroll
        for(int c = 0; c < 16; c++) a += mvn[c*16 + i] * Wq_mv[o*16 + c];
        int hh = o & 7, mm = o >> 3;
        g_Q[((size_t)(b*NH + hh)*NCH + mm*16 + i)*NSEQ + n] = a * scl;
    }
    for(int idx = t; idx < 2048; idx += 256){
        int o = idx >> 4, i = idx & 15;
        float a = 0.0f;
#pragma unroll
        for(int c = 0; c < 16; c++) a += mvn[c*16 + i] * Wkv_mv[o*16 + c];
        int kv = o >> 6, rr = o & 63, hh = rr & 7, mm = rr >> 3;
        if(kv == 0) g_K[((size_t)(b*NH + hh)*NCH + mm*16 + i)*NSEQ + n] = a;
        else        g_V[((size_t)(b*NH + hh)*NSEQ + n)*NCH + mm*16 + i] = a;
    }
    if(t < 128){
        float a = 0.0f;
#pragma unroll
        for(int c = 0; c < 64; c++) a += scn[c] * Wq_s[t*64 + c];
        qs[t] = a;
    }
    {
        float a = 0.0f;
#pragma unroll
        for(int c = 0; c < 64; c++) a += scn[c] * Wkv_s[t*64 + c];
        int kv = t >> 7, rr = t & 127;
        if(kv == 0) ks[rr] = a; else vs[rr] = a;
    }
    __syncthreads();

    if(t < 128){
        int hh = t & 7, ss = t >> 3;
        g_V[((size_t)(b*NH + hh)*NSEQ + n)*NCH + 128 + ss] = vs[t];
    }
    if(t < 64){
        int hh = t & 7, p = t >> 3;
        float ang = (float)n * exp2f(-1.5f * (float)p);
        float cs = cosf(ang), sn = sinf(ang);
        float x1 = qs[(2*p)*8 + hh], x2 = qs[(2*p+1)*8 + hh];
        size_t base = ((size_t)(b*NH + hh)*NCH + 128);
        g_Q[(base + 2*p  )*NSEQ + n] = (x1*cs - x2*sn) * scl;
        g_Q[(base + 2*p+1)*NSEQ + n] = (x1*sn + x2*cs) * scl;
    } else if(t < 128){
        int u = t - 64;
        int hh = u & 7, p = u >> 3;
        float ang = (float)n * exp2f(-1.5f * (float)p);
        float cs = cosf(ang), sn = sinf(ang);
        float x1 = ks[(2*p)*8 + hh], x2 = ks[(2*p+1)*8 + hh];
        size_t base = ((size_t)(b*NH + hh)*NCH + 128);
        g_K[(base + 2*p  )*NSEQ + n] = x1*cs - x2*sn;
        g_K[(base + 2*p+1)*NSEQ + n] = x1*sn + x2*cs;
    }
}

// ---------------- Kernel B: bias, 2x2 register-tiled projection ----------------
// 128 pairs/block, 256 threads. Thread (u = t>>2, v = t&3) computes
// pairs {u, u+64} x heads {v, v+4}: 4 LDS.128 per 16 FMA (was 8 B/FMA -> 4 B/FMA).
__global__ __launch_bounds__(256) void bias_kernel(
        const float* __restrict__ pz, const unsigned int* __restrict__ msk,
        const float* __restrict__ gamma, const float* __restrict__ beta,
        const float* __restrict__ Wpb){
    extern __shared__ float sm[];
    float* sZ    = sm;                       // [128][132]
    float* sA    = sZ + BIAS_PAIRS*132;      // [8][132]
    float* sGB   = sA + 8*132;               // G[0..7], B[8..15]
    float* sM    = sGB + 16;                 // [128]
    float* sR    = sM + 128;                 // [128]
    float* sMask = sR + 128;                 // [128]

    int t = threadIdx.x;
    int lane = t & 31, w = t >> 5;
    int pid0 = blockIdx.x * BIAS_PAIRS;
    int b  = pid0 / (NSEQ*NSEQ);
    int r0 = pid0 % (NSEQ*NSEQ);
    int i  = r0 / NSEQ;
    int j0 = r0 % NSEQ;

    // fill z tile: 128 pairs x 128 ch = 4096 float4 (coalesced; one row per warp-iter)
    const float4* zg = (const float4*)(pz + (size_t)pid0 * NCZ);
    for(int i4 = t; i4 < BIAS_PAIRS*32; i4 += 256){
        int r = i4 >> 5, c4 = i4 & 31;
        *(float4*)(sZ + r*132 + c4*4) = zg[i4];
    }
    // A = gamma * W
    for(int idx = t; idx < 1024; idx += 256){
        int h = idx >> 7, c = idx & 127;
        sA[h*132 + c] = gamma[c] * Wpb[h*NCZ + c];
    }
    // G_h, B_h: warp w reduces head w
    {
        float gs = 0.f, bs = 0.f;
#pragma unroll
        for(int k = 0; k < 4; k++){
            int c = lane + 32*k;
            float wv = Wpb[w*NCZ + c];
            gs += gamma[c]*wv;
            bs += beta[c]*wv;
        }
        gs = warpSum(gs); bs = warpSum(bs);
        if(lane == 0){ sGB[w] = gs; sGB[8+w] = bs; }
    }
    for(int p = t; p < BIAS_PAIRS; p += 256)
        sMask[p] = (msk[pid0 + p] != 0u) ? 0.0f : BIGF;
    __syncthreads();

    // LN stats: warp w handles pairs w*16..w*16+15 (independent chains -> ILP)
#pragma unroll 4
    for(int rr = 0; rr < 16; rr++){
        int p = w*16 + rr;
        float4 z4 = *(const float4*)(sZ + p*132 + lane*4);
        float s1 = z4.x + z4.y + z4.z + z4.w;
        float s2 = z4.x*z4.x + z4.y*z4.y + z4.z*z4.z + z4.w*z4.w;
        s1 = warpSum(s1); s2 = warpSum(s2);
        if(lane == 0){
            float m = s1 * (1.0f/NCZ);
            float v = s2 * (1.0f/NCZ) - m*m;
            sM[p] = m;
            sR[p] = rsqrtf(v + LNEPS);
        }
    }
    __syncthreads();

    // 2x2 projection tile
    {
        int u = t >> 2, v = t & 3;          // pairs {u, u+64}, heads {v, v+4}
        const float4* z0p = (const float4*)(sZ + u*132);
        const float4* z1p = (const float4*)(sZ + (u+64)*132);
        const float4* a0p = (const float4*)(sA + v*132);
        const float4* a1p = (const float4*)(sA + (v+4)*132);
        float a00=0.f, a01=0.f, a10=0.f, a11=0.f;
#pragma unroll
        for(int c4 = 0; c4 < 32; c4++){
            float4 za = z0p[c4], zb = z1p[c4];
            float4 wa = a0p[c4], wb = a1p[c4];
            a00 += za.x*wa.x + za.y*wa.y + za.z*wa.z + za.w*wa.w;
            a01 += za.x*wb.x + za.y*wb.y + za.z*wb.z + za.w*wb.w;
            a10 += zb.x*wa.x + zb.y*wa.y + zb.z*wa.z + zb.w*wa.w;
            a11 += zb.x*wb.x + zb.y*wb.y + zb.z*wb.z + zb.w*wb.w;
        }
        float G0 = sGB[v], G1 = sGB[v+4], B0 = sGB[8+v], B1 = sGB[8+v+4];
        float m0 = sM[u], r0s = sR[u], k0 = sMask[u];
        float m1 = sM[u+64], r1s = sR[u+64], k1 = sMask[u+64];
        float o00 = r0s*(a00 - m0*G0) + B0 + k0;
        float o01 = r0s*(a01 - m0*G1) + B1 + k0;
        float o10 = r1s*(a10 - m1*G0) + B0 + k1;
        float o11 = r1s*(a11 - m1*G1) + B1 + k1;
        size_t base0 = ((size_t)(b*NH + v  )*NSEQ + i)*NSEQ + j0;
        size_t base1 = ((size_t)(b*NH + v+4)*NSEQ + i)*NSEQ + j0;
        g_bias[base0 + u]      = o00;
        g_bias[base1 + u]      = o01;
        g_bias[base0 + u + 64] = o10;
        g_bias[base1 + u + 64] = o11;
    }
}

// ---------------- Kernel C: attention (R8/R15 body, unchanged) ----------------
__global__ __launch_bounds__(256, 2) void attn_kernel(){
    extern __shared__ float smem[];
    float* sQ = smem;                       // [144][SQP]
    float* sK = sQ + 144*SQP;               // [144][SKP]
    float* sV = sK + 144*SKP;               // [64][SVP]
    float* sP = sV + 64*SVP;                // [32][SPP]

    int qt = blockIdx.x, h = blockIdx.y, b = blockIdx.z;
    int t = threadIdx.x;
    int ty = t >> 4, tx = t & 15;
    int q0 = qt * QT;
    size_t bh = (size_t)(b*NH + h);

    const float* Qg = g_Q + bh*NCH*NSEQ;    // [c][n]
    const float* Kg = g_K + bh*NCH*NSEQ;    // [c][n]
    const float* Vg = g_V + bh*NSEQ*NCH;    // [n][c]
    const float* Bg = g_bias + (bh*NSEQ + q0)*NSEQ;

    for(int i4 = t; i4 < 144*8; i4 += 256){
        int c = i4 >> 3, qq = i4 & 7;
        *(float4*)(sQ + c*SQP + qq*4) = *(const float4*)(Qg + (size_t)c*NSEQ + q0 + qq*4);
    }

    int r0 = ty*2, r1 = ty*2 + 1;
    float m0 = -1e30f, m1 = -1e30f, l0 = 0.f, l1 = 0.f;
    float O0[9], O1[9];
#pragma unroll
    for(int k = 0; k < 9; k++){ O0[k]=0.f; O1[k]=0.f; }

    for(int jt = 0; jt < NJT; jt++){
        int j0 = jt * JTT;
        __syncthreads();
        for(int i4 = t; i4 < 144*16; i4 += 256){
            int c = i4 >> 4, jj = i4 & 15;
            *(float4*)(sK + c*SKP + jj*4) = *(const float4*)(Kg + (size_t)c*NSEQ + j0 + jj*4);
        }
        for(int i4 = t; i4 < 64*36; i4 += 256){
            int r = i4/36, c4 = i4%36;
            *(float4*)(sV + r*SVP + c4*4) = *(const float4*)(Vg + (size_t)(j0+r)*NCH + c4*4);
        }
        __syncthreads();

        float s00=0,s01=0,s02=0,s03=0,s10=0,s11=0,s12=0,s13=0;
#pragma unroll 8
        for(int c = 0; c < NCH; c++){
            float qa = sQ[c*SQP + r0];
            float qb = sQ[c*SQP + r1];
            float4 k4 = *(float4*)(sK + c*SKP + tx*4);
            s00 += qa*k4.x; s01 += qa*k4.y; s02 += qa*k4.z; s03 += qa*k4.w;
            s10 += qb*k4.x; s11 += qb*k4.y; s12 += qb*k4.z; s13 += qb*k4.w;
        }
        {
            float4 b0 = *(const float4*)(Bg + (size_t)r0*NSEQ + j0 + tx*4);
            float4 b1 = *(const float4*)(Bg + (size_t)r1*NSEQ + j0 + tx*4);
            s00+=b0.x; s01+=b0.y; s02+=b0.z; s03+=b0.w;
            s10+=b1.x; s11+=b1.y; s12+=b1.z; s13+=b1.w;
        }
        float nm0 = grpMax(fmaxf(fmaxf(s00,s01), fmaxf(s02,s03)));
        float nm1 = grpMax(fmaxf(fmaxf(s10,s11), fmaxf(s12,s13)));
        nm0 = fmaxf(m0, nm0);
        nm1 = fmaxf(m1, nm1);
        float a0 = __expf(m0 - nm0);
        float a1 = __expf(m1 - nm1);
        float p00 = __expf(s00-nm0), p01 = __expf(s01-nm0), p02 = __expf(s02-nm0), p03 = __expf(s03-nm0);
        float p10 = __expf(s10-nm1), p11 = __expf(s11-nm1), p12 = __expf(s12-nm1), p13 = __expf(s13-nm1);
        float ps0 = grpSum(p00+p01+p02+p03);
        float ps1 = grpSum(p10+p11+p12+p13);
        l0 = l0*a0 + ps0;  m0 = nm0;
        l1 = l1*a1 + ps1;  m1 = nm1;
#pragma unroll
        for(int k = 0; k < 9; k++){ O0[k] *= a0; O1[k] *= a1; }
        *(float4*)(sP + r0*SPP + tx*4) = make_float4(p00,p01,p02,p03);
        *(float4*)(sP + r1*SPP + tx*4) = make_float4(p10,p11,p12,p13);
        __syncthreads();

#pragma unroll 4
        for(int jj = 0; jj < JTT; jj++){
            float p0 = sP[r0*SPP + jj];
            float p1 = sP[r1*SPP + jj];
            const float* vr = sV + jj*SVP + tx*9;
#pragma unroll
            for(int k = 0; k < 9; k++){
                float vv = vr[k];
                O0[k] += p0*vv;
                O1[k] += p1*vv;
            }
        }
    }

    float inv0 = 1.0f/l0, inv1 = 1.0f/l1;
    float* o0 = g_Hb + ((size_t)(b*NSEQ + q0 + r0)*NH + h)*NCH + tx*9;
    float* o1 = g_Hb + ((size_t)(b*NSEQ + q0 + r1)*NH + h)*NCH + tx*9;
#pragma unroll
    for(int k = 0; k < 9; k++){ o0[k] = O0[k]*inv0; o1[k] = O1[k]*inv1; }
}

// ---------------- Kernel D: output projections (unchanged) ----------------
__global__ __launch_bounds__(256) void out_kernel(
        const float* __restrict__ Wo_mv, const float* __restrict__ Wo_s,
        float* __restrict__ out){
    int bn = blockIdx.x;
    int t = threadIdx.x;
    __shared__ float wmv[16*64];
    __shared__ float ws [64*128];
    __shared__ float hrow[NH*NCH];

    for(int i = t; i < 1024; i += 256) wmv[i] = Wo_mv[i];
    for(int i4 = t; i4 < 2048; i4 += 256)
        *(float4*)(ws + i4*4) = ((const float4*)Wo_s)[i4];
    for(int i4 = t; i4 < 288; i4 += 256)
        *(float4*)(hrow + i4*4) = ((const float4*)(g_Hb + (size_t)bn*NH*NCH))[i4];
    __syncthreads();

    {
        int o = t >> 4, i = t & 15;
        float acc = 0.0f;
#pragma unroll
        for(int hh = 0; hh < 8; hh++)
#pragma unroll
            for(int mm = 0; mm < 8; mm++)
                acc += hrow[hh*NCH + mm*16 + i] * wmv[o*64 + hh*8 + mm];
        out[(size_t)bn*256 + t] = acc;
    }
    if(t < 64){
        float acc = 0.0f;
#pragma unroll
        for(int hh = 0; hh < 8; hh++)
#pragma unroll
            for(int ss = 0; ss < 16; ss++)
                acc += hrow[hh*NCH + 128 + ss] * ws[t*128 + hh*16 + ss];
        out[(size_t)NB*NSEQ*256 + (size_t)bn*64 + t] = acc;
    }
}

// ---------------- launch ----------------
extern "C" void kernel_launch(void* const* d_in, const int* in_sizes, int n_in,
                              void* d_out, int out_size){
    const float* mv    = (const float*)d_in[0];
    const float* sca   = (const float*)d_in[1];
    const float* pz    = (const float*)d_in[2];
    const unsigned int* mask = (const unsigned int*)d_in[3];
    const float* Wq_mv = (const float*)d_in[4];
    const float* Wq_s  = (const float*)d_in[5];
    const float* Wkv_mv= (const float*)d_in[6];
    const float* Wkv_s = (const float*)d_in[7];
    const float* Wo_mv = (const float*)d_in[8];
    const float* Wo_s  = (const float*)d_in[9];
    const float* lng   = (const float*)d_in[10];
    const float* lnb   = (const float*)d_in[11];
    const float* Wpb   = (const float*)d_in[12];

    cudaFuncSetAttribute(attn_kernel, cudaFuncAttributeMaxDynamicSharedMemorySize,
                         ATTN_SMEM_FLOATS * (int)sizeof(float));
    cudaFuncSetAttribute(bias_kernel, cudaFuncAttributeMaxDynamicSharedMemorySize,
                         BIAS_SMEM_FLOATS * (int)sizeof(float));

    probe_kernel<<<1, 32>>>();    // two probes: ncu capture (4th kernel) lands on bias
    probe_kernel2<<<1, 32>>>();
    qkv_kernel<<<NB*NSEQ, 256>>>(mv, sca, Wq_mv, Wq_s, Wkv_mv, Wkv_s);
    bias_kernel<<<(NB*NSEQ*NSEQ)/BIAS_PAIRS, 256, BIAS_SMEM_FLOATS*sizeof(float)>>>(
        pz, mask, lng, lnb, Wpb);
    attn_kernel<<<dim3(NSEQ/QT, NH, NB), 256, ATTN_SMEM_FLOATS*sizeof(float)>>>();
    out_kernel<<<NB*NSEQ, 256>>>(Wo_mv, Wo_s, (float*)d_out);
}

// round 17
// speedup vs baseline: 1.0481x; 1.0481x over previous
#include <cuda_runtime.h>
#include <math.h>

#define NH 8
#define NB 2
#define NSEQ 384
#define NCZ 128
#define NCH 144            // per-head channels: 128 mv + 16 scalar
#define BIGF 100000.0f
#define LNEPS 1e-5f

#define QT 32              // q tile
#define JTT 64             // j tile
#define NJT (NSEQ/JTT)     // 6

// attn smem strides (floats)
#define SQP 36             // sQ [144][36]
#define SKP 68             // sK [144][68]
#define SVP 148            // sV [64][148]
#define SPP 68             // sP [32][68]
#define ATTN_SMEM_FLOATS (144*SQP + 144*SKP + 64*SVP + 32*SPP)

// Scratch (no cudaMalloc allowed)
__device__ float g_Qr[NB*NH*NSEQ*NCH];   // row-major staging [bh][n][c]
__device__ float g_Kr[NB*NH*NSEQ*NCH];   // row-major staging [bh][n][c]
__device__ float g_Q[NB*NH*NCH*NSEQ];    // channel-major [b][h][c][n]
__device__ float g_K[NB*NH*NCH*NSEQ];    // channel-major [b][h][c][n]
__device__ float g_V[NB*NH*NSEQ*NCH];    // row-major    [b][h][n][c]
__device__ float g_bias[NB*NH*NSEQ*NSEQ];
__device__ float g_Hb[NB*NSEQ*NH*NCH];

// ---------------- reductions ----------------
__device__ __forceinline__ float warpSum(float v){
#pragma unroll
    for(int o=16;o;o>>=1) v += __shfl_xor_sync(0xffffffffu, v, o);
    return v;
}

template<int NW>
__device__ __forceinline__ float blockSum(float v, float* red){
    int lane = threadIdx.x & 31, w = threadIdx.x >> 5;
    v = warpSum(v);
    if(lane==0) red[w] = v;
    __syncthreads();
    if(threadIdx.x < 32){
        float r = (lane < NW) ? red[lane] : 0.0f;
        r = warpSum(r);
        if(lane==0) red[0] = r;
    }
    __syncthreads();
    float r = red[0];
    __syncthreads();
    return r;
}

__device__ __forceinline__ float grpMax(float v){
#pragma unroll
    for(int o=8;o;o>>=1) v = fmaxf(v, __shfl_xor_sync(0xffffffffu, v, o));
    return v;
}
__device__ __forceinline__ float grpSum(float v){
#pragma unroll
    for(int o=8;o;o>>=1) v += __shfl_xor_sync(0xffffffffu, v, o);
    return v;
}

// ---------------- probes: 3 probes put the ncu capture slot (4th kernel) on qkv ----------------
__global__ void probe_kernel(){}
__global__ void probe_kernel2(){}
__global__ void probe_kernel3(){}

// ---------------- Kernel A: pln + QKV projections + rope (COALESCED row-major stores) ----------------
__global__ void qkv_kernel(const float* __restrict__ mv, const float* __restrict__ sca,
                           const float* __restrict__ Wq_mv, const float* __restrict__ Wq_s,
                           const float* __restrict__ Wkv_mv, const float* __restrict__ Wkv_s){
    int bn = blockIdx.x;
    int b = bn / NSEQ, n = bn % NSEQ;
    int t = threadIdx.x;
    __shared__ float mvn[256];
    __shared__ float scn[64];
    __shared__ float qs[128], ks[128], vs[128];
    __shared__ float red[32];
    const float scl = 1.0f/12.0f;  // 1/sqrt(144)

    float x = mv[(size_t)bn*256 + t];
    float s1 = blockSum<8>(x, red);
    float s2 = blockSum<8>(x*x, red);
    float m  = s1 * (1.0f/256.0f);
    float vr = s2 * (1.0f/256.0f) - m*m;
    mvn[t] = (x - m) * rsqrtf(vr + LNEPS);

    float y = (t < 64) ? sca[(size_t)bn*64 + t] : 0.0f;
    float t1 = blockSum<8>(y, red);
    float t2 = blockSum<8>(y*y, red);
    float m2 = t1 * (1.0f/64.0f);
    float v2 = t2 * (1.0f/64.0f) - m2*m2;
    float rs2 = rsqrtf(v2 + LNEPS);
    if(t < 64) scn[t] = (y - m2) * rs2;
    __syncthreads();

    // q_mv -> g_Qr row-major [bh][n][c]
    for(int idx = t; idx < 1024; idx += 256){
        int o = idx >> 4, i = idx & 15;
        float a = 0.0f;
#pragma unroll
        for(int c = 0; c < 16; c++) a += mvn[c*16 + i] * Wq_mv[o*16 + c];
        int hh = o & 7, mm = o >> 3;
        g_Qr[((size_t)(b*NH + hh)*NSEQ + n)*NCH + mm*16 + i] = a * scl;
    }
    // kv_mv -> g_Kr row-major, g_V row-major
    for(int idx = t; idx < 2048; idx += 256){
        int o = idx >> 4, i = idx & 15;
        float a = 0.0f;
#pragma unroll
        for(int c = 0; c < 16; c++) a += mvn[c*16 + i] * Wkv_mv[o*16 + c];
        int kv = o >> 6, rr = o & 63, hh = rr & 7, mm = rr >> 3;
        if(kv == 0) g_Kr[((size_t)(b*NH + hh)*NSEQ + n)*NCH + mm*16 + i] = a;
        else        g_V [((size_t)(b*NH + hh)*NSEQ + n)*NCH + mm*16 + i] = a;
    }
    if(t < 128){
        float a = 0.0f;
#pragma unroll
        for(int c = 0; c < 64; c++) a += scn[c] * Wq_s[t*64 + c];
        qs[t] = a;
    }
    {
        float a = 0.0f;
#pragma unroll
        for(int c = 0; c < 64; c++) a += scn[c] * Wkv_s[t*64 + c];
        int kv = t >> 7, rr = t & 127;
        if(kv == 0) ks[rr] = a; else vs[rr] = a;
    }
    __syncthreads();

    if(t < 128){
        int hh = t & 7, ss = t >> 3;
        g_V[((size_t)(b*NH + hh)*NSEQ + n)*NCH + 128 + ss] = vs[t];
    }
    if(t < 64){
        int hh = t & 7, p = t >> 3;
        float ang = (float)n * exp2f(-1.5f * (float)p);
        float cs = cosf(ang), sn = sinf(ang);
        float x1 = qs[(2*p)*8 + hh], x2 = qs[(2*p+1)*8 + hh];
        size_t base = ((size_t)(b*NH + hh)*NSEQ + n)*NCH + 128;
        g_Qr[base + 2*p  ] = (x1*cs - x2*sn) * scl;
        g_Qr[base + 2*p+1] = (x1*sn + x2*cs) * scl;
    } else if(t < 128){
        int u = t - 64;
        int hh = u & 7, p = u >> 3;
        float ang = (float)n * exp2f(-1.5f * (float)p);
        float cs = cosf(ang), sn = sinf(ang);
        float x1 = ks[(2*p)*8 + hh], x2 = ks[(2*p+1)*8 + hh];
        size_t base = ((size_t)(b*NH + hh)*NSEQ + n)*NCH + 128;
        g_Kr[base + 2*p  ] = x1*cs - x2*sn;
        g_Kr[base + 2*p+1] = x1*sn + x2*cs;
    }
}

// ---------------- Kernel A2: transpose [bh][n][c] -> [bh][c][n], coalesced both sides ----------------
// grid (12 n-tiles, 5 c-tiles, 32 = 16 bh x 2 tensors), block 32x8
__global__ void transpose_kernel(){
    __shared__ float tile[32][33];
    int tz = blockIdx.z;
    int bh = tz & 15;
    const float* src = (tz < 16 ? g_Qr : g_Kr) + (size_t)bh*NSEQ*NCH;
    float*       dst = (tz < 16 ? g_Q  : g_K ) + (size_t)bh*NCH*NSEQ;
    int n0 = blockIdx.x * 32, c0 = blockIdx.y * 32;
    int tx = threadIdx.x, ty = threadIdx.y;

    for(int i = ty; i < 32; i += 8){
        int c = c0 + tx;
        if(c < NCH) tile[i][tx] = src[(size_t)(n0 + i)*NCH + c];
    }
    __syncthreads();
    for(int i = ty; i < 32; i += 8){
        int c = c0 + i;
        if(c < NCH) dst[(size_t)c*NSEQ + n0 + tx] = tile[tx][i];
    }
}

// ---------------- Kernel B: bias (R15 version, measured 90us) ----------------
__global__ __launch_bounds__(256) void bias_kernel(
        const float* __restrict__ pz, const unsigned int* __restrict__ msk,
        const float* __restrict__ gamma, const float* __restrict__ beta,
        const float* __restrict__ Wpb){
    __shared__ float sZ[32*132];
    __shared__ float sA[8*132];
    __shared__ float sG[8], sB[8];
    __shared__ float sM[32];
    __shared__ float sR[32];
    __shared__ float sMask[32];

    int t = threadIdx.x;
    int lane = t & 31, w = t >> 5;
    int pid0 = blockIdx.x * 32;
    int b  = pid0 / (NSEQ*NSEQ);
    int r0 = pid0 % (NSEQ*NSEQ);
    int i  = r0 / NSEQ;
    int j0 = r0 % NSEQ;

    const float4* zg = (const float4*)(pz + (size_t)pid0 * NCZ);
    for(int i4 = t; i4 < 1024; i4 += 256){
        int r = i4 >> 5, c4 = i4 & 31;
        *(float4*)(sZ + r*132 + c4*4) = zg[i4];
    }
    for(int idx = t; idx < 1024; idx += 256){
        int h = idx >> 7, c = idx & 127;
        sA[h*132 + c] = gamma[c] * Wpb[h*NCZ + c];
    }
    {
        float gs = 0.f, bs = 0.f;
#pragma unroll
        for(int k = 0; k < 4; k++){
            int c = lane + 32*k;
            float wv = Wpb[w*NCZ + c];
            gs += gamma[c]*wv;
            bs += beta[c]*wv;
        }
        gs = warpSum(gs); bs = warpSum(bs);
        if(lane == 0){ sG[w] = gs; sB[w] = bs; }
    }
    if(t < 32) sMask[t] = (msk[pid0 + t] != 0u) ? 0.0f : BIGF;
    __syncthreads();

#pragma unroll
    for(int rr = 0; rr < 4; rr++){
        int p = w*4 + rr;
        float4 z4 = *(const float4*)(sZ + p*132 + lane*4);
        float s1 = z4.x + z4.y + z4.z + z4.w;
        float s2 = z4.x*z4.x + z4.y*z4.y + z4.z*z4.z + z4.w*z4.w;
        s1 = warpSum(s1); s2 = warpSum(s2);
        if(lane == 0){
            float m = s1 * (1.0f/NCZ);
            float v = s2 * (1.0f/NCZ) - m*m;
            sM[p] = m;
            sR[p] = rsqrtf(v + LNEPS);
        }
    }
    __syncthreads();

    {
        int p = t >> 3, h = t & 7;
        const float4* zp = (const float4*)(sZ + p*132);
        const float4* ap = (const float4*)(sA + h*132);
        float acc = 0.f;
#pragma unroll
        for(int c4 = 0; c4 < 32; c4++){
            float4 z4 = zp[c4], a4 = ap[c4];
            acc += z4.x*a4.x + z4.y*a4.y + z4.z*a4.z + z4.w*a4.w;
        }
        float out = sR[p]*(acc - sM[p]*sG[h]) + sB[h] + sMask[p];
        g_bias[((size_t)(b*NH + h)*NSEQ + i)*NSEQ + j0 + p] = out;
    }
}

// ---------------- Kernel C: attention (R8/R15 body, unchanged) ----------------
__global__ __launch_bounds__(256, 2) void attn_kernel(){
    extern __shared__ float smem[];
    float* sQ = smem;                       // [144][SQP]
    float* sK = sQ + 144*SQP;               // [144][SKP]
    float* sV = sK + 144*SKP;               // [64][SVP]
    float* sP = sV + 64*SVP;                // [32][SPP]

    int qt = blockIdx.x, h = blockIdx.y, b = blockIdx.z;
    int t = threadIdx.x;
    int ty = t >> 4, tx = t & 15;
    int q0 = qt * QT;
    size_t bh = (size_t)(b*NH + h);

    const float* Qg = g_Q + bh*NCH*NSEQ;    // [c][n]
    const float* Kg = g_K + bh*NCH*NSEQ;    // [c][n]
    const float* Vg = g_V + bh*NSEQ*NCH;    // [n][c]
    const float* Bg = g_bias + (bh*NSEQ + q0)*NSEQ;

    for(int i4 = t; i4 < 144*8; i4 += 256){
        int c = i4 >> 3, qq = i4 & 7;
        *(float4*)(sQ + c*SQP + qq*4) = *(const float4*)(Qg + (size_t)c*NSEQ + q0 + qq*4);
    }

    int r0 = ty*2, r1 = ty*2 + 1;
    float m0 = -1e30f, m1 = -1e30f, l0 = 0.f, l1 = 0.f;
    float O0[9], O1[9];
#pragma unroll
    for(int k = 0; k < 9; k++){ O0[k]=0.f; O1[k]=0.f; }

    for(int jt = 0; jt < NJT; jt++){
        int j0 = jt * JTT;
        __syncthreads();
        for(int i4 = t; i4 < 144*16; i4 += 256){
            int c = i4 >> 4, jj = i4 & 15;
            *(float4*)(sK + c*SKP + jj*4) = *(const float4*)(Kg + (size_t)c*NSEQ + j0 + jj*4);
        }
        for(int i4 = t; i4 < 64*36; i4 += 256){
            int r = i4/36, c4 = i4%36;
            *(float4*)(sV + r*SVP + c4*4) = *(const float4*)(Vg + (size_t)(j0+r)*NCH + c4*4);
        }
        __syncthreads();

        float s00=0,s01=0,s02=0,s03=0,s10=0,s11=0,s12=0,s13=0;
#pragma unroll 8
        for(int c = 0; c < NCH; c++){
            float qa = sQ[c*SQP + r0];
            float qb = sQ[c*SQP + r1];
            float4 k4 = *(float4*)(sK + c*SKP + tx*4);
            s00 += qa*k4.x; s01 += qa*k4.y; s02 += qa*k4.z; s03 += qa*k4.w;
            s10 += qb*k4.x; s11 += qb*k4.y; s12 += qb*k4.z; s13 += qb*k4.w;
        }
        {
            float4 b0 = *(const float4*)(Bg + (size_t)r0*NSEQ + j0 + tx*4);
            float4 b1 = *(const float4*)(Bg + (size_t)r1*NSEQ + j0 + tx*4);
            s00+=b0.x; s01+=b0.y; s02+=b0.z; s03+=b0.w;
            s10+=b1.x; s11+=b1.y; s12+=b1.z; s13+=b1.w;
        }
        float nm0 = grpMax(fmaxf(fmaxf(s00,s01), fmaxf(s02,s03)));
        float nm1 = grpMax(fmaxf(fmaxf(s10,s11), fmaxf(s12,s13)));
        nm0 = fmaxf(m0, nm0);
        nm1 = fmaxf(m1, nm1);
        float a0 = __expf(m0 - nm0);
        float a1 = __expf(m1 - nm1);
        float p00 = __expf(s00-nm0), p01 = __expf(s01-nm0), p02 = __expf(s02-nm0), p03 = __expf(s03-nm0);
        float p10 = __expf(s10-nm1), p11 = __expf(s11-nm1), p12 = __expf(s12-nm1), p13 = __expf(s13-nm1);
        float ps0 = grpSum(p00+p01+p02+p03);
        float ps1 = grpSum(p10+p11+p12+p13);
        l0 = l0*a0 + ps0;  m0 = nm0;
        l1 = l1*a1 + ps1;  m1 = nm1;
#pragma unroll
        for(int k = 0; k < 9; k++){ O0[k] *= a0; O1[k] *= a1; }
        *(float4*)(sP + r0*SPP + tx*4) = make_float4(p00,p01,p02,p03);
        *(float4*)(sP + r1*SPP + tx*4) = make_float4(p10,p11,p12,p13);
        __syncthreads();

#pragma unroll 4
        for(int jj = 0; jj < JTT; jj++){
            float p0 = sP[r0*SPP + jj];
            float p1 = sP[r1*SPP + jj];
            const float* vr = sV + jj*SVP + tx*9;
#pragma unroll
            for(int k = 0; k < 9; k++){
                float vv = vr[k];
                O0[k] += p0*vv;
                O1[k] += p1*vv;
            }
        }
    }

    float inv0 = 1.0f/l0, inv1 = 1.0f/l1;
    float* o0 = g_Hb + ((size_t)(b*NSEQ + q0 + r0)*NH + h)*NCH + tx*9;
    float* o1 = g_Hb + ((size_t)(b*NSEQ + q0 + r1)*NH + h)*NCH + tx*9;
#pragma unroll
    for(int k = 0; k < 9; k++){ o0[k] = O0[k]*inv0; o1[k] = O1[k]*inv1; }
}

// ---------------- Kernel D: output projections (unchanged) ----------------
__global__ __launch_bounds__(256) void out_kernel(
        const float* __restrict__ Wo_mv, const float* __restrict__ Wo_s,
        float* __restrict__ out){
    int bn = blockIdx.x;
    int t = threadIdx.x;
    __shared__ float wmv[16*64];
    __shared__ float ws [64*128];
    __shared__ float hrow[NH*NCH];

    for(int i = t; i < 1024; i += 256) wmv[i] = Wo_mv[i];
    for(int i4 = t; i4 < 2048; i4 += 256)
        *(float4*)(ws + i4*4) = ((const float4*)Wo_s)[i4];
    for(int i4 = t; i4 < 288; i4 += 256)
        *(float4*)(hrow + i4*4) = ((const float4*)(g_Hb + (size_t)bn*NH*NCH))[i4];
    __syncthreads();

    {
        int o = t >> 4, i = t & 15;
        float acc = 0.0f;
#pragma unroll
        for(int hh = 0; hh < 8; hh++)
#pragma unroll
            for(int mm = 0; mm < 8; mm++)
                acc += hrow[hh*NCH + mm*16 + i] * wmv[o*64 + hh*8 + mm];
        out[(size_t)bn*256 + t] = acc;
    }
    if(t < 64){
        float acc = 0.0f;
#pragma unroll
        for(int hh = 0; hh < 8; hh++)
#pragma unroll
            for(int ss = 0; ss < 16; ss++)
                acc += hrow[hh*NCH + 128 + ss] * ws[t*128 + hh*16 + ss];
        out[(size_t)NB*NSEQ*256 + (size_t)bn*64 + t] = acc;
    }
}

// ---------------- launch ----------------
extern "C" void kernel_launch(void* const* d_in, const int* in_sizes, int n_in,
                              void* d_out, int out_size){
    const float* mv    = (const float*)d_in[0];
    const float* sca   = (const float*)d_in[1];
    const float* pz    = (const float*)d_in[2];
    const unsigned int* mask = (const unsigned int*)d_in[3];
    const float* Wq_mv = (const float*)d_in[4];
    const float* Wq_s  = (const float*)d_in[5];
    const float* Wkv_mv= (const float*)d_in[6];
    const float* Wkv_s = (const float*)d_in[7];
    const float* Wo_mv = (const float*)d_in[8];
    const float* Wo_s  = (const float*)d_in[9];
    const float* lng   = (const float*)d_in[10];
    const float* lnb   = (const float*)d_in[11];
    const float* Wpb   = (const float*)d_in[12];

    cudaFuncSetAttribute(attn_kernel, cudaFuncAttributeMaxDynamicSharedMemorySize,
                         ATTN_SMEM_FLOATS * (int)sizeof(float));

    probe_kernel<<<1, 32>>>();    // 3 probes: ncu capture (4th kernel) lands on qkv
    probe_kernel2<<<1, 32>>>();
    probe_kernel3<<<1, 32>>>();
    qkv_kernel<<<NB*NSEQ, 256>>>(mv, sca, Wq_mv, Wq_s, Wkv_mv, Wkv_s);
    transpose_kernel<<<dim3(NSEQ/32, 5, 32), dim3(32, 8)>>>();
    bias_kernel<<<(NB*NSEQ*NSEQ)/32, 256>>>(pz, mask, lng, lnb, Wpb);
    attn_kernel<<<dim3(NSEQ/QT, NH, NB), 256, ATTN_SMEM_FLOATS*sizeof(float)>>>();
    out_kernel<<<NB*NSEQ, 256>>>(Wo_mv, Wo_s, (float*)d_out);
}